// round 6
// baseline (speedup 1.0000x reference)
#include <cuda_runtime.h>

#define DEV __device__ __forceinline__

constexpr int B    = 8;
constexpr int N    = 8192;
constexpr int M    = 2500;
constexpr int SPP  = 250;    // M / P(=10)

// joint tile: 256 queries (pred) x 1024 candidates (gt) per block
constexpr int QCH   = 10;              // query chunks (10*256 = 2560 >= 2500)
constexpr int QPB2  = 256;             // queries per block
constexpr int GCH   = 8;               // gt chunks per batch (8*1024 = 8192)
constexpr int CPT   = 8;               // candidates per thread (4 packs)
constexpr int CPW   = 32 * CPT;        // 256 candidates per warp
constexpr int WCH   = N / CPW;         // 32 warp-level candidate chunks
constexpr int NBLK_C = B * QCH * GCH;  // 640
constexpr int NBLK_F = 20 * B;         // 160
constexpr int NBLK_1 = NBLK_C + NBLK_F;

constexpr int FB_P = (B * M + 511) / 512;       // 40
constexpr int FB_G = (B * N / 4) / 512;         // 32 (float4 per thread)

constexpr float BIG = 3.2e38f;

// Partials — every slot written unconditionally; no init kernel, no atomics.
__device__ float g_rowPart[WCH * B * M];    // d^2 row-min per warp-candidate-chunk
__device__ float g_colPart[QCH * B * N];    // d^2 col-min per query-chunk
__device__ float g_fffp[NBLK_F * 11];
__device__ float g_sum2[FB_P + FB_G];

// ---- packed fp32x2 helpers ----
DEV unsigned long long pack2(float lo, float hi) {
    unsigned long long r;
    asm("mov.b64 %0, {%1, %2};" : "=l"(r) : "f"(lo), "f"(hi));
    return r;
}
DEV void unpack2(unsigned long long v, float& lo, float& hi) {
    asm("mov.b64 {%0, %1}, %2;" : "=f"(lo), "=f"(hi) : "l"(v));
}
DEV unsigned long long fma2(unsigned long long a, unsigned long long b, unsigned long long c) {
    unsigned long long d;
    asm("fma.rn.f32x2 %0, %1, %2, %3;" : "=l"(d) : "l"(a), "l"(b), "l"(c));
    return d;
}
DEV unsigned long long add2(unsigned long long a, unsigned long long b) {
    unsigned long long d;
    asm("add.rn.f32x2 %0, %1, %2;" : "=l"(d) : "l"(a), "l"(b));
    return d;
}

DEV float blockReduceSum(float v) {
    __shared__ float sred[32];
    #pragma unroll
    for (int o = 16; o > 0; o >>= 1) v += __shfl_down_sync(0xffffffffu, v, o);
    int lane = threadIdx.x & 31, w = threadIdx.x >> 5;
    if (lane == 0) sred[w] = v;
    __syncthreads();
    int nw = (blockDim.x + 31) >> 5;
    v = (threadIdx.x < (unsigned)nw) ? sred[threadIdx.x] : 0.0f;
    if (w == 0) {
        #pragma unroll
        for (int o = 16; o > 0; o >>= 1) v += __shfl_down_sync(0xffffffffu, v, o);
    }
    __syncthreads();
    return v;
}

// ================= K1: joint chamfer tiles + fff partials =================
__global__ void __launch_bounds__(128) k_mega(const float* __restrict__ pred,
                                              const float* __restrict__ gt,
                                              const float* __restrict__ fff) {
    int bid = blockIdx.x;
    int tid = threadIdx.x;

    if (bid >= NBLK_C) {
        // ---------------- fff partial-sums block ----------------
        int fb = bid - NBLK_C;
        int b  = fb / 20;
        int m  = (fb % 20) * 128 + tid;
        float v[11];
        #pragma unroll
        for (int i = 0; i < 11; i++) v[i] = 0.0f;
        if (m < M) {
            int idx = (b * M + m) * 3;
            float E = fff[idx], F = fff[idx + 1], G = fff[idx + 2];
            float A2  = fmaxf(E * G - F * F, 0.0f);
            float A   = sqrtf(A2);
            float inv = 1.0f / (A2 + 1e-20f);
            v[0] = E;        v[1] = G;        v[2] = inv;
            v[3] = E * inv;  v[4] = E * E * inv;
            v[5] = G * inv;  v[6] = G * G * inv;
            v[7] = F * F * inv;
            float d = E - G; v[8] = d * d * inv;
            if ((b & 1) == 0) {
                int idx2 = ((b + 1) * M + m) * 3;
                float E2 = fff[idx2], F2 = fff[idx2 + 1], G2 = fff[idx2 + 2];
                float dE = E - E2, dF = F - F2, dG = G - G2;
                v[9] = dE * dE + 2.0f * dF * dF + dG * dG;
            }
            v[10] = A;
        }
        #pragma unroll
        for (int k = 0; k < 11; k++) {
            float s = blockReduceSum(v[k]);
            if (tid == 0) g_fffp[fb * 11 + k] = s;
        }
        return;
    }

    // ---------------- joint chamfer tile ----------------
    __shared__ float4 qs[QPB2][2];     // {-2qx,-2qx,-2qy,-2qy},{-2qz,-2qz,qn,qn}
    __shared__ float  rowBuf[4][QPB2]; // per-warp row-min per query

    int gi = bid & (GCH - 1);
    int qi = (bid >> 3) % QCH;
    int b  = bid / (GCH * QCH);
    int w    = tid >> 5;
    int lane = tid & 31;
    int qbase = qi * QPB2;

    // stage queries (pred chunk), pre-negated/duplicated; pad with BIG
    for (int s = tid; s < QPB2; s += 128) {
        int m = qbase + s;
        if (m < M) {
            const float* p = pred + (size_t)(b * M + m) * 3;
            float x = p[0], y = p[1], z = p[2];
            float n = x * x + y * y + z * z;
            qs[s][0] = make_float4(-2.f * x, -2.f * x, -2.f * y, -2.f * y);
            qs[s][1] = make_float4(-2.f * z, -2.f * z, n, n);
        } else {
            qs[s][0] = make_float4(0.f, 0.f, 0.f, 0.f);
            qs[s][1] = make_float4(0.f, 0.f, BIG, BIG);
        }
    }

    // load this thread's 8 candidates into registers (coalesced float4 x6)
    int cbase = gi * (4 * CPW) + w * CPW + lane * CPT;
    const float4* gsrc = (const float4*)(gt + (size_t)(b * N + cbase) * 3);
    float4 f0 = gsrc[0], f1 = gsrc[1], f2 = gsrc[2];
    float4 f3 = gsrc[3], f4 = gsrc[4], f5 = gsrc[5];
    float cf[24] = {f0.x,f0.y,f0.z,f0.w, f1.x,f1.y,f1.z,f1.w,
                    f2.x,f2.y,f2.z,f2.w, f3.x,f3.y,f3.z,f3.w,
                    f4.x,f4.y,f4.z,f4.w, f5.x,f5.y,f5.z,f5.w};
    unsigned long long cx[4], cy[4], cz[4], gn[4];
    float gns[8];
    #pragma unroll
    for (int k = 0; k < 4; k++) {
        float x0 = cf[6*k+0], y0 = cf[6*k+1], z0 = cf[6*k+2];
        float x1 = cf[6*k+3], y1 = cf[6*k+4], z1 = cf[6*k+5];
        cx[k] = pack2(x0, x1);
        cy[k] = pack2(y0, y1);
        cz[k] = pack2(z0, z1);
        float n0 = x0*x0 + y0*y0 + z0*z0;
        float n1 = x1*x1 + y1*y1 + z1*z1;
        gn[k] = pack2(n0, n1);
        gns[2*k] = n0; gns[2*k+1] = n1;
    }
    float cm[8];
    #pragma unroll
    for (int k = 0; k < 8; k++) cm[k] = BIG;
    __syncthreads();

    // main loop over queries (broadcast smem reads)
    #pragma unroll 2
    for (int s = 0; s < QPB2; s++) {
        float4 a = qs[s][0];
        float4 c = qs[s][1];
        unsigned long long qx2 = pack2(a.x, a.y);
        unsigned long long qy2 = pack2(a.z, a.w);
        unsigned long long qz2 = pack2(c.x, c.y);
        unsigned long long qn2 = pack2(c.z, c.w);
        float rv = BIG;
        #pragma unroll
        for (int k = 0; k < 4; k++) {
            unsigned long long t = fma2(cx[k], qx2,
                                   fma2(cy[k], qy2,
                                   fma2(cz[k], qz2, qn2)));   // qn - 2 q.c
            float tl, th; unpack2(t, tl, th);
            cm[2*k]   = fminf(cm[2*k],   tl);
            cm[2*k+1] = fminf(cm[2*k+1], th);
            unsigned long long r = add2(t, gn[k]);            // full d^2
            float rl, rh; unpack2(r, rl, rh);
            rv = fminf(rv, fminf(rl, rh));
        }
        #pragma unroll
        for (int o = 16; o > 0; o >>= 1)
            rv = fminf(rv, __shfl_xor_sync(0xffffffffu, rv, o));
        if (lane == 0) rowBuf[w][s] = rv;
    }

    // col partials: add gn, coalesced float4 writes (thread's 8 cands contiguous)
    {
        float4* outc = (float4*)(g_colPart + (size_t)qi * (B * N) + b * N + cbase);
        outc[0] = make_float4(fmaxf(cm[0] + gns[0], 0.f), fmaxf(cm[1] + gns[1], 0.f),
                              fmaxf(cm[2] + gns[2], 0.f), fmaxf(cm[3] + gns[3], 0.f));
        outc[1] = make_float4(fmaxf(cm[4] + gns[4], 0.f), fmaxf(cm[5] + gns[5], 0.f),
                              fmaxf(cm[6] + gns[6], 0.f), fmaxf(cm[7] + gns[7], 0.f));
    }
    __syncthreads();

    // row partials: 4 warps x 256 queries, coalesced
    for (int idx = tid; idx < 4 * QPB2; idx += 128) {
        int ww = idx >> 8;            // owning warp
        int s  = idx & (QPB2 - 1);
        int m  = qbase + s;
        if (m < M) {
            int ch = gi * 4 + ww;     // warp-level candidate chunk [0,32)
            g_rowPart[(size_t)ch * (B * M) + b * M + m] = rowBuf[ww][s];
        }
    }
}

// ================= K2: finish — min over chunks, clamp, partial sums =========
__global__ void __launch_bounds__(512) k_finish() {
    int bid = blockIdx.x;
    int tid = threadIdx.x;
    float d = 0.0f;
    if (bid < FB_P) {
        int qi = bid * 512 + tid;          // [0, B*M)
        if (qi < B * M) {
            float f = g_rowPart[qi];
            #pragma unroll
            for (int ch = 1; ch < WCH; ch++)
                f = fminf(f, g_rowPart[(size_t)ch * (B * M) + qi]);
            d = fmaxf(f, 0.0f);
        }
    } else {
        int gi = (bid - FB_P) * 512 + tid;  // [0, B*N/4), exact
        const float4* cp = (const float4*)g_colPart;
        float4 f = cp[gi];
        #pragma unroll
        for (int ch = 1; ch < QCH; ch++) {
            float4 v = cp[(size_t)ch * (B * N / 4) + gi];
            f.x = fminf(f.x, v.x); f.y = fminf(f.y, v.y);
            f.z = fminf(f.z, v.z); f.w = fminf(f.w, v.w);
        }
        d = f.x + f.y + f.z + f.w;   // already clamped at write
    }
    float s = blockReduceSum(d);
    if (tid == 0) g_sum2[bid] = s;
}

// ================= K3: final combine =================
__global__ void __launch_bounds__(512) k_final(const float* __restrict__ A_gt,
                                               float* __restrict__ out) {
    int tid = threadIdx.x;
    __shared__ float sA[NBLK_F];
    __shared__ float acc[12];

    #pragma unroll
    for (int k = 0; k < 10; k++) {
        float v = (tid < NBLK_F) ? g_fffp[tid * 11 + k] : 0.0f;
        float s = blockReduceSum(v);
        if (tid == 0) acc[k] = s;
    }
    {
        float v = (tid < FB_P) ? g_sum2[tid] : 0.0f;
        float s = blockReduceSum(v);
        if (tid == 0) acc[10] = s;
        v = (tid < FB_G) ? g_sum2[FB_P + tid] : 0.0f;
        s = blockReduceSum(v);
        if (tid == 0) acc[11] = s;
    }
    if (tid < NBLK_F) sA[tid] = g_fffp[tid * 11 + 10];
    __syncthreads();

    if (tid == 0) {
        float BM = (float)(B * M);
        float L_chd = acc[10] / BM + acc[11] / (float)(B * N);
        float sE = acc[0], sG = acc[1], sInv = acc[2];
        float sEinv = acc[3], sE2inv = acc[4], sGinv = acc[5], sG2inv = acc[6];
        float sF2inv = acc[7], sStretch = acc[8], sMc = acc[9];
        float mE = sE / BM, mG = sG / BM;
        float L_E  = (sE2inv - 2.0f * mE * sEinv + mE * mE * sInv) / BM;
        float L_G  = (sG2inv - 2.0f * mG * sGinv + mG * mG * sInv) / BM;
        float L_F  = sF2inv  / BM;
        float L_st = sStretch / BM;
        float L_mc = sMc / (0.5f * BM);
        float L_ol = 0.0f;
        for (int b = 0; b < B; b++) {
            float at = 0.0f;
            for (int j = 0; j < 20; j++) at += sA[b * 20 + j];
            at *= (1.0f / (float)SPP);
            float r = fmaxf(at - A_gt[b], 0.0f);
            L_ol += r * r;
        }
        L_ol *= (1.0f / (float)B);
        out[0] = L_chd + L_mc + L_F + L_E + L_G + L_st + L_ol;
    }
}

extern "C" void kernel_launch(void* const* d_in, const int* in_sizes, int n_in,
                              void* d_out, int out_size) {
    (void)in_sizes; (void)n_in; (void)out_size;
    const float* pc_gt   = (const float*)d_in[0];
    const float* pc_pred = (const float*)d_in[1];
    const float* fffp    = (const float*)d_in[2];
    const float* A_gt    = (const float*)d_in[3];
    float* out = (float*)d_out;

    k_mega  <<<NBLK_1, 128>>>(pc_pred, pc_gt, fffp);
    k_finish<<<FB_P + FB_G, 512>>>();
    k_final <<<1, 512>>>(A_gt, out);
}

// round 7
// speedup vs baseline: 1.2688x; 1.2688x over previous
#include <cuda_runtime.h>

#define DEV __device__ __forceinline__

constexpr int B    = 8;
constexpr int N    = 8192;
constexpr int M    = 2500;
constexpr int SPP  = 250;    // M / P(=10)

// joint tile: 128 queries (pred) x 1024 candidates (gt) per block
constexpr int QCH   = 20;              // query chunks (20*128 = 2560 >= 2500)
constexpr int QPB2  = 128;             // queries per block
constexpr int GCH   = 8;               // gt chunks per batch (8*1024 = 8192)
constexpr int CPT   = 8;               // candidates per thread (4 packs)
constexpr int CPW   = 32 * CPT;        // 256 candidates per warp
constexpr int WCH   = N / CPW;         // 32 warp-level candidate chunks
constexpr int NBLK_F = 20 * B;         // 160 fff blocks (first in grid)
constexpr int NBLK_C = B * QCH * GCH;  // 1280 chamfer blocks
constexpr int NBLK_1 = NBLK_F + NBLK_C;

constexpr int FB_P = (B * M + 511) / 512;       // 40
constexpr int FB_G = (B * N / 4) / 512;         // 32 (float4 per thread)

constexpr float BIG = 3.2e38f;

// Partials — every slot written unconditionally; no init kernel, no atomics.
__device__ float g_rowPart[WCH * B * M];    // d^2 row-min per warp-candidate-chunk
__device__ float g_colPart[QCH * B * N];    // (qn - 2qc) col-min per query-chunk
__device__ float g_fffp[NBLK_F * 11];
__device__ float g_sum2[FB_P + FB_G];

// ---- packed fp32x2 helpers ----
DEV unsigned long long pack2(float lo, float hi) {
    unsigned long long r;
    asm("mov.b64 %0, {%1, %2};" : "=l"(r) : "f"(lo), "f"(hi));
    return r;
}
DEV void unpack2(unsigned long long v, float& lo, float& hi) {
    asm("mov.b64 {%0, %1}, %2;" : "=f"(lo), "=f"(hi) : "l"(v));
}
DEV unsigned long long fma2(unsigned long long a, unsigned long long b, unsigned long long c) {
    unsigned long long d;
    asm("fma.rn.f32x2 %0, %1, %2, %3;" : "=l"(d) : "l"(a), "l"(b), "l"(c));
    return d;
}
DEV unsigned long long add2(unsigned long long a, unsigned long long b) {
    unsigned long long d;
    asm("add.rn.f32x2 %0, %1, %2;" : "=l"(d) : "l"(a), "l"(b));
    return d;
}
DEV unsigned warpMinU32(unsigned v) {
    unsigned r;
    asm("redux.sync.min.u32 %0, %1, 0xffffffff;" : "=r"(r) : "r"(v));
    return r;
}

DEV float blockReduceSum(float v) {
    __shared__ float sred[32];
    #pragma unroll
    for (int o = 16; o > 0; o >>= 1) v += __shfl_down_sync(0xffffffffu, v, o);
    int lane = threadIdx.x & 31, w = threadIdx.x >> 5;
    if (lane == 0) sred[w] = v;
    __syncthreads();
    int nw = (blockDim.x + 31) >> 5;
    v = (threadIdx.x < (unsigned)nw) ? sred[threadIdx.x] : 0.0f;
    if (w == 0) {
        #pragma unroll
        for (int o = 16; o > 0; o >>= 1) v += __shfl_down_sync(0xffffffffu, v, o);
    }
    __syncthreads();
    return v;
}

// ================= K1: fff partials (front) + joint chamfer tiles =================
__global__ void __launch_bounds__(128) k_mega(const float* __restrict__ pred,
                                              const float* __restrict__ gt,
                                              const float* __restrict__ fff) {
    int bid = blockIdx.x;
    int tid = threadIdx.x;

    if (bid < NBLK_F) {
        // ---------------- fff partial-sums block ----------------
        int fb = bid;
        int b  = fb / 20;
        int m  = (fb % 20) * 128 + tid;
        float v[11];
        #pragma unroll
        for (int i = 0; i < 11; i++) v[i] = 0.0f;
        if (m < M) {
            int idx = (b * M + m) * 3;
            float E = fff[idx], F = fff[idx + 1], G = fff[idx + 2];
            float A2  = fmaxf(E * G - F * F, 0.0f);
            float A   = sqrtf(A2);
            float inv = 1.0f / (A2 + 1e-20f);
            v[0] = E;        v[1] = G;        v[2] = inv;
            v[3] = E * inv;  v[4] = E * E * inv;
            v[5] = G * inv;  v[6] = G * G * inv;
            v[7] = F * F * inv;
            float d = E - G; v[8] = d * d * inv;
            if ((b & 1) == 0) {
                int idx2 = ((b + 1) * M + m) * 3;
                float E2 = fff[idx2], F2 = fff[idx2 + 1], G2 = fff[idx2 + 2];
                float dE = E - E2, dF = F - F2, dG = G - G2;
                v[9] = dE * dE + 2.0f * dF * dF + dG * dG;
            }
            v[10] = A;
        }
        #pragma unroll
        for (int k = 0; k < 11; k++) {
            float s = blockReduceSum(v[k]);
            if (tid == 0) g_fffp[fb * 11 + k] = s;
        }
        return;
    }

    // ---------------- joint chamfer tile ----------------
    __shared__ float4 qs[QPB2][2];     // {-2qx,-2qx,-2qy,-2qy},{-2qz,-2qz,qn,qn}
    __shared__ float  rowBuf[4][QPB2]; // per-warp row-min per query

    int cbid = bid - NBLK_F;
    int gi = cbid & (GCH - 1);
    int qi = (cbid >> 3) % QCH;
    int b  = cbid / (GCH * QCH);
    int w    = tid >> 5;
    int lane = tid & 31;
    int qbase = qi * QPB2;

    // stage queries: pre-negated/duplicated; pad with BIG norm
    if (tid < QPB2) {
        int m = qbase + tid;
        if (m < M) {
            const float* p = pred + (size_t)(b * M + m) * 3;
            float x = p[0], y = p[1], z = p[2];
            float n = x * x + y * y + z * z;
            qs[tid][0] = make_float4(-2.f * x, -2.f * x, -2.f * y, -2.f * y);
            qs[tid][1] = make_float4(-2.f * z, -2.f * z, n, n);
        } else {
            qs[tid][0] = make_float4(0.f, 0.f, 0.f, 0.f);
            qs[tid][1] = make_float4(0.f, 0.f, BIG, BIG);
        }
    }

    // this thread's 8 candidates -> registers (coalesced float4 x6)
    int cbase = gi * (4 * CPW) + w * CPW + lane * CPT;
    const float4* gsrc = (const float4*)(gt + (size_t)(b * N + cbase) * 3);
    float4 f0 = gsrc[0], f1 = gsrc[1], f2 = gsrc[2];
    float4 f3 = gsrc[3], f4 = gsrc[4], f5 = gsrc[5];
    float cf[24] = {f0.x,f0.y,f0.z,f0.w, f1.x,f1.y,f1.z,f1.w,
                    f2.x,f2.y,f2.z,f2.w, f3.x,f3.y,f3.z,f3.w,
                    f4.x,f4.y,f4.z,f4.w, f5.x,f5.y,f5.z,f5.w};
    unsigned long long cx[4], cy[4], cz[4], gn[4];
    float gns[8];
    #pragma unroll
    for (int k = 0; k < 4; k++) {
        float x0 = cf[6*k+0], y0 = cf[6*k+1], z0 = cf[6*k+2];
        float x1 = cf[6*k+3], y1 = cf[6*k+4], z1 = cf[6*k+5];
        cx[k] = pack2(x0, x1);
        cy[k] = pack2(y0, y1);
        cz[k] = pack2(z0, z1);
        float n0 = x0*x0 + y0*y0 + z0*z0;
        float n1 = x1*x1 + y1*y1 + z1*z1;
        gn[k] = pack2(n0, n1);
        gns[2*k] = n0; gns[2*k+1] = n1;
    }
    float cm[8];
    #pragma unroll
    for (int k = 0; k < 8; k++) cm[k] = BIG;
    __syncthreads();

    // main loop: queries via broadcast LDS, candidates in registers
    #pragma unroll 2
    for (int s = 0; s < QPB2; s++) {
        float4 a = qs[s][0];
        float4 c = qs[s][1];
        unsigned long long qx2 = pack2(a.x, a.y);
        unsigned long long qy2 = pack2(a.z, a.w);
        unsigned long long qz2 = pack2(c.x, c.y);
        unsigned long long qn2 = pack2(c.z, c.w);
        float r01, r23, r45, r67;
        {
            unsigned long long t = fma2(cx[0], qx2, fma2(cy[0], qy2, fma2(cz[0], qz2, qn2)));
            float tl, th; unpack2(t, tl, th);
            cm[0] = fminf(cm[0], tl);
            cm[1] = fminf(cm[1], th);
            float rl, rh; unpack2(add2(t, gn[0]), rl, rh);
            r01 = fminf(rl, rh);
        }
        {
            unsigned long long t = fma2(cx[1], qx2, fma2(cy[1], qy2, fma2(cz[1], qz2, qn2)));
            float tl, th; unpack2(t, tl, th);
            cm[2] = fminf(cm[2], tl);
            cm[3] = fminf(cm[3], th);
            float rl, rh; unpack2(add2(t, gn[1]), rl, rh);
            r23 = fminf(rl, rh);
        }
        {
            unsigned long long t = fma2(cx[2], qx2, fma2(cy[2], qy2, fma2(cz[2], qz2, qn2)));
            float tl, th; unpack2(t, tl, th);
            cm[4] = fminf(cm[4], tl);
            cm[5] = fminf(cm[5], th);
            float rl, rh; unpack2(add2(t, gn[2]), rl, rh);
            r45 = fminf(rl, rh);
        }
        {
            unsigned long long t = fma2(cx[3], qx2, fma2(cy[3], qy2, fma2(cz[3], qz2, qn2)));
            float tl, th; unpack2(t, tl, th);
            cm[6] = fminf(cm[6], tl);
            cm[7] = fminf(cm[7], th);
            float rl, rh; unpack2(add2(t, gn[3]), rl, rh);
            r67 = fminf(rl, rh);
        }
        float rv = fminf(fminf(r01, r23), fminf(r45, r67));
        rv = fmaxf(rv, 0.0f);                              // d^2 >= 0, enables u32 min
        unsigned rm = warpMinU32(__float_as_uint(rv));     // single cross-lane reduce
        if (lane == 0) rowBuf[w][s] = __uint_as_float(rm);
    }

    // col partials: add gn at the end, clamp, coalesced float4 writes
    {
        float4* outc = (float4*)(g_colPart + (size_t)qi * (B * N) + b * N + cbase);
        outc[0] = make_float4(fmaxf(cm[0] + gns[0], 0.f), fmaxf(cm[1] + gns[1], 0.f),
                              fmaxf(cm[2] + gns[2], 0.f), fmaxf(cm[3] + gns[3], 0.f));
        outc[1] = make_float4(fmaxf(cm[4] + gns[4], 0.f), fmaxf(cm[5] + gns[5], 0.f),
                              fmaxf(cm[6] + gns[6], 0.f), fmaxf(cm[7] + gns[7], 0.f));
    }
    __syncthreads();

    // row partials: 4 warps x 128 queries, coalesced
    for (int idx = tid; idx < 4 * QPB2; idx += 128) {
        int ww = idx >> 7;                 // owning warp
        int s  = idx & (QPB2 - 1);
        int m  = qbase + s;
        if (m < M) {
            int ch = gi * 4 + ww;          // warp-level candidate chunk [0,32)
            g_rowPart[(size_t)ch * (B * M) + b * M + m] = rowBuf[ww][s];
        }
    }
}

// ================= K2: finish — min over chunks, partial sums =========
__global__ void __launch_bounds__(512) k_finish() {
    int bid = blockIdx.x;
    int tid = threadIdx.x;
    float d = 0.0f;
    if (bid < FB_P) {
        int qi = bid * 512 + tid;          // [0, B*M)
        if (qi < B * M) {
            float f = g_rowPart[qi];
            #pragma unroll
            for (int ch = 1; ch < WCH; ch++)
                f = fminf(f, g_rowPart[(size_t)ch * (B * M) + qi]);
            d = f;                          // already clamped at write
        }
    } else {
        int gi = (bid - FB_P) * 512 + tid;  // [0, B*N/4), exact
        const float4* cp = (const float4*)g_colPart;
        float4 f = cp[gi];
        #pragma unroll
        for (int ch = 1; ch < QCH; ch++) {
            float4 v = cp[(size_t)ch * (B * N / 4) + gi];
            f.x = fminf(f.x, v.x); f.y = fminf(f.y, v.y);
            f.z = fminf(f.z, v.z); f.w = fminf(f.w, v.w);
        }
        d = f.x + f.y + f.z + f.w;          // already clamped at write
    }
    float s = blockReduceSum(d);
    if (tid == 0) g_sum2[bid] = s;
}

// ================= K3: final combine =================
__global__ void __launch_bounds__(512) k_final(const float* __restrict__ A_gt,
                                               float* __restrict__ out) {
    int tid = threadIdx.x;
    __shared__ float sA[NBLK_F];
    __shared__ float acc[12];

    #pragma unroll
    for (int k = 0; k < 10; k++) {
        float v = (tid < NBLK_F) ? g_fffp[tid * 11 + k] : 0.0f;
        float s = blockReduceSum(v);
        if (tid == 0) acc[k] = s;
    }
    {
        float v = (tid < FB_P) ? g_sum2[tid] : 0.0f;
        float s = blockReduceSum(v);
        if (tid == 0) acc[10] = s;
        v = (tid < FB_G) ? g_sum2[FB_P + tid] : 0.0f;
        s = blockReduceSum(v);
        if (tid == 0) acc[11] = s;
    }
    if (tid < NBLK_F) sA[tid] = g_fffp[tid * 11 + 10];
    __syncthreads();

    if (tid == 0) {
        float BM = (float)(B * M);
        float L_chd = acc[10] / BM + acc[11] / (float)(B * N);
        float sE = acc[0], sG = acc[1], sInv = acc[2];
        float sEinv = acc[3], sE2inv = acc[4], sGinv = acc[5], sG2inv = acc[6];
        float sF2inv = acc[7], sStretch = acc[8], sMc = acc[9];
        float mE = sE / BM, mG = sG / BM;
        float L_E  = (sE2inv - 2.0f * mE * sEinv + mE * mE * sInv) / BM;
        float L_G  = (sG2inv - 2.0f * mG * sGinv + mG * mG * sInv) / BM;
        float L_F  = sF2inv  / BM;
        float L_st = sStretch / BM;
        float L_mc = sMc / (0.5f * BM);
        float L_ol = 0.0f;
        for (int b = 0; b < B; b++) {
            float at = 0.0f;
            for (int j = 0; j < 20; j++) at += sA[b * 20 + j];
            at *= (1.0f / (float)SPP);
            float r = fmaxf(at - A_gt[b], 0.0f);
            L_ol += r * r;
        }
        L_ol *= (1.0f / (float)B);
        out[0] = L_chd + L_mc + L_F + L_E + L_G + L_st + L_ol;
    }
}

extern "C" void kernel_launch(void* const* d_in, const int* in_sizes, int n_in,
                              void* d_out, int out_size) {
    (void)in_sizes; (void)n_in; (void)out_size;
    const float* pc_gt   = (const float*)d_in[0];
    const float* pc_pred = (const float*)d_in[1];
    const float* fffp    = (const float*)d_in[2];
    const float* A_gt    = (const float*)d_in[3];
    float* out = (float*)d_out;

    k_mega  <<<NBLK_1, 128>>>(pc_pred, pc_gt, fffp);
    k_finish<<<FB_P + FB_G, 512>>>();
    k_final <<<1, 512>>>(A_gt, out);
}

// round 8
// speedup vs baseline: 1.3432x; 1.0586x over previous
#include <cuda_runtime.h>

#define DEV __device__ __forceinline__

constexpr int B    = 8;
constexpr int N    = 8192;
constexpr int M    = 2500;
constexpr int SPP  = 250;    // M / P(=10)

// joint tile: 160 queries (pred) x 1024 candidates (gt) per block
constexpr int QCH   = 16;              // query chunks (16*160 = 2560 >= 2500)
constexpr int QPB2  = 160;             // queries per block
constexpr int GCH   = 8;               // gt chunks per batch (8*1024 = 8192)
constexpr int CPT   = 8;               // candidates per thread (4 packs)
constexpr int CPW   = 32 * CPT;        // 256 candidates per warp
constexpr int WCH   = N / CPW;         // 32 warp-level candidate chunks
constexpr int NBLK_F = 20 * B;         // 160 fff blocks (front of grid)
constexpr int NBLK_C = B * QCH * GCH;  // 1024 chamfer blocks
constexpr int NBLK_1 = NBLK_F + NBLK_C;  // 1184 = 148 SMs x 8 CTAs: ONE wave

constexpr int FB_P = (B * M + 511) / 512;       // 40
constexpr int FB_G = (B * N / 4) / 512;         // 32 (float4 per thread)

constexpr float BIG = 3.2e38f;

// Partials — every slot written unconditionally; no init kernel, no atomics.
__device__ float g_rowPart[WCH * B * M];    // d^2 row-min per warp-candidate-chunk
__device__ float g_colPart[QCH * B * N];    // (qn - 2qc) col-min per query-chunk
__device__ float g_fffp[NBLK_F * 11];
__device__ float g_sum2[FB_P + FB_G];

// ---- packed fp32x2 helpers ----
DEV unsigned long long pack2(float lo, float hi) {
    unsigned long long r;
    asm("mov.b64 %0, {%1, %2};" : "=l"(r) : "f"(lo), "f"(hi));
    return r;
}
DEV void unpack2(unsigned long long v, float& lo, float& hi) {
    asm("mov.b64 {%0, %1}, %2;" : "=f"(lo), "=f"(hi) : "l"(v));
}
DEV unsigned long long fma2(unsigned long long a, unsigned long long b, unsigned long long c) {
    unsigned long long d;
    asm("fma.rn.f32x2 %0, %1, %2, %3;" : "=l"(d) : "l"(a), "l"(b), "l"(c));
    return d;
}
DEV unsigned long long add2(unsigned long long a, unsigned long long b) {
    unsigned long long d;
    asm("add.rn.f32x2 %0, %1, %2;" : "=l"(d) : "l"(a), "l"(b));
    return d;
}
DEV unsigned warpMinU32(unsigned v) {
    unsigned r;
    asm("redux.sync.min.u32 %0, %1, 0xffffffff;" : "=r"(r) : "r"(v));
    return r;
}

DEV float blockReduceSum(float v) {
    __shared__ float sred[32];
    #pragma unroll
    for (int o = 16; o > 0; o >>= 1) v += __shfl_down_sync(0xffffffffu, v, o);
    int lane = threadIdx.x & 31, w = threadIdx.x >> 5;
    if (lane == 0) sred[w] = v;
    __syncthreads();
    int nw = (blockDim.x + 31) >> 5;
    v = (threadIdx.x < (unsigned)nw) ? sred[threadIdx.x] : 0.0f;
    if (w == 0) {
        #pragma unroll
        for (int o = 16; o > 0; o >>= 1) v += __shfl_down_sync(0xffffffffu, v, o);
    }
    __syncthreads();
    return v;
}

// ================= K1: fff partials (front) + joint chamfer tiles =================
__global__ void __launch_bounds__(128, 8) k_mega(const float* __restrict__ pred,
                                                 const float* __restrict__ gt,
                                                 const float* __restrict__ fff) {
    int bid = blockIdx.x;
    int tid = threadIdx.x;

    if (bid < NBLK_F) {
        // ---------------- fff partial-sums block ----------------
        int fb = bid;
        int b  = fb / 20;
        int m  = (fb % 20) * 128 + tid;
        float v[11];
        #pragma unroll
        for (int i = 0; i < 11; i++) v[i] = 0.0f;
        if (m < M) {
            int idx = (b * M + m) * 3;
            float E = fff[idx], F = fff[idx + 1], G = fff[idx + 2];
            float A2  = fmaxf(E * G - F * F, 0.0f);
            float A   = sqrtf(A2);
            float inv = 1.0f / (A2 + 1e-20f);
            v[0] = E;        v[1] = G;        v[2] = inv;
            v[3] = E * inv;  v[4] = E * E * inv;
            v[5] = G * inv;  v[6] = G * G * inv;
            v[7] = F * F * inv;
            float d = E - G; v[8] = d * d * inv;
            if ((b & 1) == 0) {
                int idx2 = ((b + 1) * M + m) * 3;
                float E2 = fff[idx2], F2 = fff[idx2 + 1], G2 = fff[idx2 + 2];
                float dE = E - E2, dF = F - F2, dG = G - G2;
                v[9] = dE * dE + 2.0f * dF * dF + dG * dG;
            }
            v[10] = A;
        }
        #pragma unroll
        for (int k = 0; k < 11; k++) {
            float s = blockReduceSum(v[k]);
            if (tid == 0) g_fffp[fb * 11 + k] = s;
        }
        return;
    }

    // ---------------- joint chamfer tile ----------------
    __shared__ float4 qs[QPB2][2];     // {-2qx,-2qx,-2qy,-2qy},{-2qz,-2qz,qn,qn}
    __shared__ float  rowBuf[4][QPB2]; // per-warp row-min per query

    int cbid = bid - NBLK_F;
    int gi = cbid & (GCH - 1);
    int qi = (cbid >> 3) & (QCH - 1);
    int b  = cbid >> 7;                // / (GCH*QCH)
    int w    = tid >> 5;
    int lane = tid & 31;
    int qbase = qi * QPB2;

    // stage queries: pre-negated/duplicated; pad with BIG norm
    for (int s = tid; s < QPB2; s += 128) {
        int m = qbase + s;
        if (m < M) {
            const float* p = pred + (size_t)(b * M + m) * 3;
            float x = p[0], y = p[1], z = p[2];
            float n = x * x + y * y + z * z;
            qs[s][0] = make_float4(-2.f * x, -2.f * x, -2.f * y, -2.f * y);
            qs[s][1] = make_float4(-2.f * z, -2.f * z, n, n);
        } else {
            qs[s][0] = make_float4(0.f, 0.f, 0.f, 0.f);
            qs[s][1] = make_float4(0.f, 0.f, BIG, BIG);
        }
    }

    // this thread's 8 candidates -> registers (coalesced float4 x6)
    int cbase = gi * (4 * CPW) + w * CPW + lane * CPT;
    const float4* gsrc = (const float4*)(gt + (size_t)(b * N + cbase) * 3);
    float4 f0 = gsrc[0], f1 = gsrc[1], f2 = gsrc[2];
    float4 f3 = gsrc[3], f4 = gsrc[4], f5 = gsrc[5];
    float cf[24] = {f0.x,f0.y,f0.z,f0.w, f1.x,f1.y,f1.z,f1.w,
                    f2.x,f2.y,f2.z,f2.w, f3.x,f3.y,f3.z,f3.w,
                    f4.x,f4.y,f4.z,f4.w, f5.x,f5.y,f5.z,f5.w};
    unsigned long long cx[4], cy[4], cz[4], gn[4];
    float gns[8];
    #pragma unroll
    for (int k = 0; k < 4; k++) {
        float x0 = cf[6*k+0], y0 = cf[6*k+1], z0 = cf[6*k+2];
        float x1 = cf[6*k+3], y1 = cf[6*k+4], z1 = cf[6*k+5];
        cx[k] = pack2(x0, x1);
        cy[k] = pack2(y0, y1);
        cz[k] = pack2(z0, z1);
        float n0 = x0*x0 + y0*y0 + z0*z0;
        float n1 = x1*x1 + y1*y1 + z1*z1;
        gn[k] = pack2(n0, n1);
        gns[2*k] = n0; gns[2*k+1] = n1;
    }
    float cm[8];
    #pragma unroll
    for (int k = 0; k < 8; k++) cm[k] = BIG;
    __syncthreads();

    // main loop: queries via broadcast LDS, candidates in registers
    #pragma unroll 4
    for (int s = 0; s < QPB2; s++) {
        float4 a = qs[s][0];
        float4 c = qs[s][1];
        unsigned long long qx2 = pack2(a.x, a.y);
        unsigned long long qy2 = pack2(a.z, a.w);
        unsigned long long qz2 = pack2(c.x, c.y);
        unsigned long long qn2 = pack2(c.z, c.w);

        unsigned long long t0 = fma2(cx[0], qx2, fma2(cy[0], qy2, fma2(cz[0], qz2, qn2)));
        unsigned long long t1 = fma2(cx[1], qx2, fma2(cy[1], qy2, fma2(cz[1], qz2, qn2)));
        unsigned long long t2 = fma2(cx[2], qx2, fma2(cy[2], qy2, fma2(cz[2], qz2, qn2)));
        unsigned long long t3 = fma2(cx[3], qx2, fma2(cy[3], qy2, fma2(cz[3], qz2, qn2)));

        float tl, th;
        unpack2(t0, tl, th); cm[0] = fminf(cm[0], tl); cm[1] = fminf(cm[1], th);
        unpack2(t1, tl, th); cm[2] = fminf(cm[2], tl); cm[3] = fminf(cm[3], th);
        unpack2(t2, tl, th); cm[4] = fminf(cm[4], tl); cm[5] = fminf(cm[5], th);
        unpack2(t3, tl, th); cm[6] = fminf(cm[6], tl); cm[7] = fminf(cm[7], th);

        float r0l, r0h, r1l, r1h, r2l, r2h, r3l, r3h;
        unpack2(add2(t0, gn[0]), r0l, r0h);
        unpack2(add2(t1, gn[1]), r1l, r1h);
        unpack2(add2(t2, gn[2]), r2l, r2h);
        unpack2(add2(t3, gn[3]), r3l, r3h);
        float rv = fminf(fminf(fminf(r0l, r0h), fminf(r1l, r1h)),
                         fminf(fminf(r2l, r2h), fminf(r3l, r3h)));
        // u32 min treats tiny negatives as huge -> harmless (error ~1e-7 abs)
        unsigned rm = warpMinU32(__float_as_uint(rv));
        if (lane == 0) rowBuf[w][s] = __uint_as_float(rm);
    }

    // col partials: add gn at the end, clamp, coalesced float4 writes
    {
        float4* outc = (float4*)(g_colPart + (size_t)qi * (B * N) + b * N + cbase);
        outc[0] = make_float4(fmaxf(cm[0] + gns[0], 0.f), fmaxf(cm[1] + gns[1], 0.f),
                              fmaxf(cm[2] + gns[2], 0.f), fmaxf(cm[3] + gns[3], 0.f));
        outc[1] = make_float4(fmaxf(cm[4] + gns[4], 0.f), fmaxf(cm[5] + gns[5], 0.f),
                              fmaxf(cm[6] + gns[6], 0.f), fmaxf(cm[7] + gns[7], 0.f));
    }
    __syncthreads();

    // row partials: 4 warps x 160 queries, coalesced
    for (int idx = tid; idx < 4 * QPB2; idx += 128) {
        int ww = idx / QPB2;               // owning warp
        int s  = idx - ww * QPB2;
        int m  = qbase + s;
        if (m < M) {
            int ch = gi * 4 + ww;          // warp-level candidate chunk [0,32)
            g_rowPart[(size_t)ch * (B * M) + b * M + m] = rowBuf[ww][s];
        }
    }
}

// ================= K2: finish — min over chunks, partial sums =========
__global__ void __launch_bounds__(512) k_finish() {
    int bid = blockIdx.x;
    int tid = threadIdx.x;
    float d = 0.0f;
    if (bid < FB_P) {
        int qi = bid * 512 + tid;          // [0, B*M)
        if (qi < B * M) {
            float f = g_rowPart[qi];
            #pragma unroll
            for (int ch = 1; ch < WCH; ch++)
                f = fminf(f, g_rowPart[(size_t)ch * (B * M) + qi]);
            d = fmaxf(f, 0.0f);
        }
    } else {
        int gi = (bid - FB_P) * 512 + tid;  // [0, B*N/4), exact
        const float4* cp = (const float4*)g_colPart;
        float4 f = cp[gi];
        #pragma unroll
        for (int ch = 1; ch < QCH; ch++) {
            float4 v = cp[(size_t)ch * (B * N / 4) + gi];
            f.x = fminf(f.x, v.x); f.y = fminf(f.y, v.y);
            f.z = fminf(f.z, v.z); f.w = fminf(f.w, v.w);
        }
        d = f.x + f.y + f.z + f.w;          // already clamped at write
    }
    float s = blockReduceSum(d);
    if (tid == 0) g_sum2[bid] = s;
}

// ================= K3: final combine =================
__global__ void __launch_bounds__(512) k_final(const float* __restrict__ A_gt,
                                               float* __restrict__ out) {
    int tid = threadIdx.x;
    __shared__ float sA[NBLK_F];
    __shared__ float acc[12];

    #pragma unroll
    for (int k = 0; k < 10; k++) {
        float v = (tid < NBLK_F) ? g_fffp[tid * 11 + k] : 0.0f;
        float s = blockReduceSum(v);
        if (tid == 0) acc[k] = s;
    }
    {
        float v = (tid < FB_P) ? g_sum2[tid] : 0.0f;
        float s = blockReduceSum(v);
        if (tid == 0) acc[10] = s;
        v = (tid < FB_G) ? g_sum2[FB_P + tid] : 0.0f;
        s = blockReduceSum(v);
        if (tid == 0) acc[11] = s;
    }
    if (tid < NBLK_F) sA[tid] = g_fffp[tid * 11 + 10];
    __syncthreads();

    if (tid == 0) {
        float BM = (float)(B * M);
        float L_chd = acc[10] / BM + acc[11] / (float)(B * N);
        float sE = acc[0], sG = acc[1], sInv = acc[2];
        float sEinv = acc[3], sE2inv = acc[4], sGinv = acc[5], sG2inv = acc[6];
        float sF2inv = acc[7], sStretch = acc[8], sMc = acc[9];
        float mE = sE / BM, mG = sG / BM;
        float L_E  = (sE2inv - 2.0f * mE * sEinv + mE * mE * sInv) / BM;
        float L_G  = (sG2inv - 2.0f * mG * sGinv + mG * mG * sInv) / BM;
        float L_F  = sF2inv  / BM;
        float L_st = sStretch / BM;
        float L_mc = sMc / (0.5f * BM);
        float L_ol = 0.0f;
        for (int b = 0; b < B; b++) {
            float at = 0.0f;
            for (int j = 0; j < 20; j++) at += sA[b * 20 + j];
            at *= (1.0f / (float)SPP);
            float r = fmaxf(at - A_gt[b], 0.0f);
            L_ol += r * r;
        }
        L_ol *= (1.0f / (float)B);
        out[0] = L_chd + L_mc + L_F + L_E + L_G + L_st + L_ol;
    }
}

extern "C" void kernel_launch(void* const* d_in, const int* in_sizes, int n_in,
                              void* d_out, int out_size) {
    (void)in_sizes; (void)n_in; (void)out_size;
    const float* pc_gt   = (const float*)d_in[0];
    const float* pc_pred = (const float*)d_in[1];
    const float* fffp    = (const float*)d_in[2];
    const float* A_gt    = (const float*)d_in[3];
    float* out = (float*)d_out;

    k_mega  <<<NBLK_1, 128>>>(pc_pred, pc_gt, fffp);
    k_finish<<<FB_P + FB_G, 512>>>();
    k_final <<<1, 512>>>(A_gt, out);
}

// round 9
// speedup vs baseline: 1.3765x; 1.0248x over previous
#include <cuda_runtime.h>

#define DEV __device__ __forceinline__

constexpr int B    = 8;
constexpr int N    = 8192;
constexpr int M    = 2500;
constexpr int SPP  = 250;    // M / P(=10)

// joint tile: 68 queries x 1024 candidates per block; grid = 148 SMs x 16 exactly
constexpr int QCH   = 37;              // query chunks (37*68 = 2516 >= 2500)
constexpr int QPB2  = 68;              // queries per block
constexpr int GCH   = 8;               // gt chunks per batch (8*1024 = 8192)
constexpr int CPT   = 8;               // candidates per thread (4 packs)
constexpr int CPW   = 32 * CPT;        // 256 candidates per warp
constexpr int WCH   = N / CPW;         // 32 warp-level candidate chunks
constexpr int NBLK_C = B * QCH * GCH;  // 2368 = 148 * 16: two perfectly uniform waves

constexpr int FB_F = 5 * B;                     // 40 fff blocks (512 thr each)
constexpr int FB_P = (B * M + 511) / 512;       // 40
constexpr int FB_G = (B * N / 4) / 512;         // 32 (float4 per thread)

constexpr float BIG = 3.2e38f;

// Partials — every slot written unconditionally; no init kernel, no atomics.
__device__ float g_rowPart[WCH * B * M];          // d^2 row-min per warp-cand-chunk
__device__ float g_colPart[(size_t)QCH * B * N];  // (qn - 2qc) col-min per query-chunk
__device__ float g_fffp[FB_F * 11];
__device__ float g_sum2[FB_P + FB_G];

// ---- packed fp32x2 helpers ----
DEV unsigned long long pack2(float lo, float hi) {
    unsigned long long r;
    asm("mov.b64 %0, {%1, %2};" : "=l"(r) : "f"(lo), "f"(hi));
    return r;
}
DEV void unpack2(unsigned long long v, float& lo, float& hi) {
    asm("mov.b64 {%0, %1}, %2;" : "=f"(lo), "=f"(hi) : "l"(v));
}
DEV unsigned long long fma2(unsigned long long a, unsigned long long b, unsigned long long c) {
    unsigned long long d;
    asm("fma.rn.f32x2 %0, %1, %2, %3;" : "=l"(d) : "l"(a), "l"(b), "l"(c));
    return d;
}
DEV unsigned long long add2(unsigned long long a, unsigned long long b) {
    unsigned long long d;
    asm("add.rn.f32x2 %0, %1, %2;" : "=l"(d) : "l"(a), "l"(b));
    return d;
}
DEV unsigned warpMinU32(unsigned v) {
    unsigned r;
    asm("redux.sync.min.u32 %0, %1, 0xffffffff;" : "=r"(r) : "r"(v));
    return r;
}

DEV float blockReduceSum(float v) {
    __shared__ float sred[32];
    #pragma unroll
    for (int o = 16; o > 0; o >>= 1) v += __shfl_down_sync(0xffffffffu, v, o);
    int lane = threadIdx.x & 31, w = threadIdx.x >> 5;
    if (lane == 0) sred[w] = v;
    __syncthreads();
    int nw = (blockDim.x + 31) >> 5;
    v = (threadIdx.x < (unsigned)nw) ? sred[threadIdx.x] : 0.0f;
    if (w == 0) {
        #pragma unroll
        for (int o = 16; o > 0; o >>= 1) v += __shfl_down_sync(0xffffffffu, v, o);
    }
    __syncthreads();
    return v;
}

// ================= K1: pure chamfer, perfectly uniform blocks =================
__global__ void __launch_bounds__(128, 8) k_mega(const float* __restrict__ pred,
                                                 const float* __restrict__ gt) {
    int bid = blockIdx.x;
    int tid = threadIdx.x;

    __shared__ ulonglong2 qs[QPB2][2];   // [0]={qx2,qy2} [1]={qz2,qn2} (pre-packed)
    __shared__ float      rowBuf[4][QPB2];

    int gi = bid & (GCH - 1);
    int qi = (bid >> 3) % QCH;
    int b  = bid / (GCH * QCH);
    int w    = tid >> 5;
    int lane = tid & 31;
    int qbase = qi * QPB2;

    // stage queries pre-packed; pad with BIG norm
    if (tid < QPB2) {
        int m = qbase + tid;
        float x = 0.f, y = 0.f, z = 0.f, n = BIG;
        if (m < M) {
            const float* p = pred + (size_t)(b * M + m) * 3;
            x = p[0]; y = p[1]; z = p[2];
            n = x * x + y * y + z * z;
        }
        ulonglong2 u0, u1;
        u0.x = pack2(-2.f * x, -2.f * x);
        u0.y = pack2(-2.f * y, -2.f * y);
        u1.x = pack2(-2.f * z, -2.f * z);
        u1.y = pack2(n, n);
        qs[tid][0] = u0;
        qs[tid][1] = u1;
    }

    // this thread's 8 candidates -> registers (coalesced float4 x6)
    int cbase = gi * (4 * CPW) + w * CPW + lane * CPT;
    const float4* gsrc = (const float4*)(gt + (size_t)(b * N + cbase) * 3);
    float4 f0 = gsrc[0], f1 = gsrc[1], f2 = gsrc[2];
    float4 f3 = gsrc[3], f4 = gsrc[4], f5 = gsrc[5];
    float cf[24] = {f0.x,f0.y,f0.z,f0.w, f1.x,f1.y,f1.z,f1.w,
                    f2.x,f2.y,f2.z,f2.w, f3.x,f3.y,f3.z,f3.w,
                    f4.x,f4.y,f4.z,f4.w, f5.x,f5.y,f5.z,f5.w};
    unsigned long long cx[4], cy[4], cz[4], gn[4];
    #pragma unroll
    for (int k = 0; k < 4; k++) {
        float x0 = cf[6*k+0], y0 = cf[6*k+1], z0 = cf[6*k+2];
        float x1 = cf[6*k+3], y1 = cf[6*k+4], z1 = cf[6*k+5];
        cx[k] = pack2(x0, x1);
        cy[k] = pack2(y0, y1);
        cz[k] = pack2(z0, z1);
        gn[k] = pack2(x0*x0 + y0*y0 + z0*z0, x1*x1 + y1*y1 + z1*z1);
    }
    float cm[8];
    #pragma unroll
    for (int k = 0; k < 8; k++) cm[k] = BIG;
    __syncthreads();

    // main loop: queries via broadcast LDS (pre-packed), candidates in registers
    #pragma unroll 4
    for (int s = 0; s < QPB2; s++) {
        ulonglong2 a = qs[s][0];
        ulonglong2 c = qs[s][1];
        unsigned long long qx2 = a.x, qy2 = a.y, qz2 = c.x, qn2 = c.y;

        unsigned long long t0 = fma2(cx[0], qx2, fma2(cy[0], qy2, fma2(cz[0], qz2, qn2)));
        unsigned long long t1 = fma2(cx[1], qx2, fma2(cy[1], qy2, fma2(cz[1], qz2, qn2)));
        unsigned long long t2 = fma2(cx[2], qx2, fma2(cy[2], qy2, fma2(cz[2], qz2, qn2)));
        unsigned long long t3 = fma2(cx[3], qx2, fma2(cy[3], qy2, fma2(cz[3], qz2, qn2)));

        float tl, th;
        unpack2(t0, tl, th); cm[0] = fminf(cm[0], tl); cm[1] = fminf(cm[1], th);
        unpack2(t1, tl, th); cm[2] = fminf(cm[2], tl); cm[3] = fminf(cm[3], th);
        unpack2(t2, tl, th); cm[4] = fminf(cm[4], tl); cm[5] = fminf(cm[5], th);
        unpack2(t3, tl, th); cm[6] = fminf(cm[6], tl); cm[7] = fminf(cm[7], th);

        float r0l, r0h, r1l, r1h, r2l, r2h, r3l, r3h;
        unpack2(add2(t0, gn[0]), r0l, r0h);
        unpack2(add2(t1, gn[1]), r1l, r1h);
        unpack2(add2(t2, gn[2]), r2l, r2h);
        unpack2(add2(t3, gn[3]), r3l, r3h);
        float rv = fminf(fminf(fminf(r0l, r0h), fminf(r1l, r1h)),
                         fminf(fminf(r2l, r2h), fminf(r3l, r3h)));
        // u32 min treats tiny negatives as huge -> harmless (error ~1e-7 abs)
        unsigned rm = warpMinU32(__float_as_uint(rv));
        if (lane == 0) rowBuf[w][s] = __uint_as_float(rm);
    }

    // col partials: add gn (unpacked here), clamp, coalesced float4 writes
    {
        float n0, n1, n2, n3, n4, n5, n6, n7;
        unpack2(gn[0], n0, n1); unpack2(gn[1], n2, n3);
        unpack2(gn[2], n4, n5); unpack2(gn[3], n6, n7);
        float4* outc = (float4*)(g_colPart + (size_t)qi * (B * N) + b * N + cbase);
        outc[0] = make_float4(fmaxf(cm[0] + n0, 0.f), fmaxf(cm[1] + n1, 0.f),
                              fmaxf(cm[2] + n2, 0.f), fmaxf(cm[3] + n3, 0.f));
        outc[1] = make_float4(fmaxf(cm[4] + n4, 0.f), fmaxf(cm[5] + n5, 0.f),
                              fmaxf(cm[6] + n6, 0.f), fmaxf(cm[7] + n7, 0.f));
    }
    __syncthreads();

    // row partials: 4 warps x 68 queries, coalesced
    for (int idx = tid; idx < 4 * QPB2; idx += 128) {
        int ww = idx / QPB2;
        int s  = idx - ww * QPB2;
        int m  = qbase + s;
        if (m < M) {
            int ch = gi * 4 + ww;          // warp-level candidate chunk [0,32)
            g_rowPart[(size_t)ch * (B * M) + b * M + m] = rowBuf[ww][s];
        }
    }
}

// ================= K2: finish — fff partials + min over chunks =========
__global__ void __launch_bounds__(512) k_finish(const float* __restrict__ fff) {
    int bid = blockIdx.x;
    int tid = threadIdx.x;

    if (bid < FB_F) {
        // ---------------- fff partial-sums block (512 thr) ----------------
        int b = bid / 5;
        int m = (bid % 5) * 512 + tid;
        float v[11];
        #pragma unroll
        for (int i = 0; i < 11; i++) v[i] = 0.0f;
        if (m < M) {
            int idx = (b * M + m) * 3;
            float E = fff[idx], F = fff[idx + 1], G = fff[idx + 2];
            float A2  = fmaxf(E * G - F * F, 0.0f);
            float A   = sqrtf(A2);
            float inv = 1.0f / (A2 + 1e-20f);
            v[0] = E;        v[1] = G;        v[2] = inv;
            v[3] = E * inv;  v[4] = E * E * inv;
            v[5] = G * inv;  v[6] = G * G * inv;
            v[7] = F * F * inv;
            float d = E - G; v[8] = d * d * inv;
            if ((b & 1) == 0) {
                int idx2 = ((b + 1) * M + m) * 3;
                float E2 = fff[idx2], F2 = fff[idx2 + 1], G2 = fff[idx2 + 2];
                float dE = E - E2, dF = F - F2, dG = G - G2;
                v[9] = dE * dE + 2.0f * dF * dF + dG * dG;
            }
            v[10] = A;
        }
        #pragma unroll
        for (int k = 0; k < 11; k++) {
            float s = blockReduceSum(v[k]);
            if (tid == 0) g_fffp[bid * 11 + k] = s;
        }
        return;
    }

    int fb = bid - FB_F;
    float d = 0.0f;
    if (fb < FB_P) {
        int qi = fb * 512 + tid;           // [0, B*M)
        if (qi < B * M) {
            float f = g_rowPart[qi];
            #pragma unroll
            for (int ch = 1; ch < WCH; ch++)
                f = fminf(f, g_rowPart[(size_t)ch * (B * M) + qi]);
            d = fmaxf(f, 0.0f);
        }
    } else {
        int gi = (fb - FB_P) * 512 + tid;  // [0, B*N/4), exact
        const float4* cp = (const float4*)g_colPart;
        float4 f = cp[gi];
        #pragma unroll
        for (int ch = 1; ch < QCH; ch++) {
            float4 v = cp[(size_t)ch * (B * N / 4) + gi];
            f.x = fminf(f.x, v.x); f.y = fminf(f.y, v.y);
            f.z = fminf(f.z, v.z); f.w = fminf(f.w, v.w);
        }
        d = f.x + f.y + f.z + f.w;          // already clamped at write
    }
    float s = blockReduceSum(d);
    if (tid == 0) g_sum2[fb] = s;
}

// ================= K3: final combine =================
__global__ void __launch_bounds__(512) k_final(const float* __restrict__ A_gt,
                                               float* __restrict__ out) {
    int tid = threadIdx.x;
    __shared__ float sA[FB_F];
    __shared__ float acc[12];

    #pragma unroll
    for (int k = 0; k < 10; k++) {
        float v = (tid < FB_F) ? g_fffp[tid * 11 + k] : 0.0f;
        float s = blockReduceSum(v);
        if (tid == 0) acc[k] = s;
    }
    {
        float v = (tid < FB_P) ? g_sum2[tid] : 0.0f;
        float s = blockReduceSum(v);
        if (tid == 0) acc[10] = s;
        v = (tid < FB_G) ? g_sum2[FB_P + tid] : 0.0f;
        s = blockReduceSum(v);
        if (tid == 0) acc[11] = s;
    }
    if (tid < FB_F) sA[tid] = g_fffp[tid * 11 + 10];
    __syncthreads();

    if (tid == 0) {
        float BM = (float)(B * M);
        float L_chd = acc[10] / BM + acc[11] / (float)(B * N);
        float sE = acc[0], sG = acc[1], sInv = acc[2];
        float sEinv = acc[3], sE2inv = acc[4], sGinv = acc[5], sG2inv = acc[6];
        float sF2inv = acc[7], sStretch = acc[8], sMc = acc[9];
        float mE = sE / BM, mG = sG / BM;
        float L_E  = (sE2inv - 2.0f * mE * sEinv + mE * mE * sInv) / BM;
        float L_G  = (sG2inv - 2.0f * mG * sGinv + mG * mG * sInv) / BM;
        float L_F  = sF2inv  / BM;
        float L_st = sStretch / BM;
        float L_mc = sMc / (0.5f * BM);
        float L_ol = 0.0f;
        for (int b = 0; b < B; b++) {
            float at = 0.0f;
            for (int j = 0; j < 5; j++) at += sA[b * 5 + j];
            at *= (1.0f / (float)SPP);
            float r = fmaxf(at - A_gt[b], 0.0f);
            L_ol += r * r;
        }
        L_ol *= (1.0f / (float)B);
        out[0] = L_chd + L_mc + L_F + L_E + L_G + L_st + L_ol;
    }
}

extern "C" void kernel_launch(void* const* d_in, const int* in_sizes, int n_in,
                              void* d_out, int out_size) {
    (void)in_sizes; (void)n_in; (void)out_size;
    const float* pc_gt   = (const float*)d_in[0];
    const float* pc_pred = (const float*)d_in[1];
    const float* fffp    = (const float*)d_in[2];
    const float* A_gt    = (const float*)d_in[3];
    float* out = (float*)d_out;

    k_mega  <<<NBLK_C, 128>>>(pc_pred, pc_gt);
    k_finish<<<FB_F + FB_P + FB_G, 512>>>(fffp);
    k_final <<<1, 512>>>(A_gt, out);
}